// round 17
// baseline (speedup 1.0000x reference)
#include <cuda_runtime.h>
#include <cuda_bf16.h>

// out[b,c,t,l] = (x[b,c,i0,l] + x[b,c,i1,l] + x[b,c,i2,l]) / 3
// x: (32, 2, 24, 32768) fp32, out: (32, 2, 30, 32768) fp32
//
// Write-width experiment: each thread owns 8 consecutive floats.
// Loads: plain float4 pairs (compiler-scheduled, default policy - preserves
// cross-replay L2 warm hits). Stores: one st.global.cs.v8.b32 (STG.256) per
// output row -> half the store instructions, 1KB contiguous per warp per
// instruction. Banded 2-row sliding window (16 float4 live).
// TPB=128, grid (32,64) = 2048 CTAs (proven best shape).

#define NV 24
#define NT 30
#define L  32768
#define L4 (L / 4)          // 8192 float4 per row
#define TPB 128

__device__ __forceinline__ void stg256_cs(float4* p, const float4& r0, const float4& r1) {
    asm volatile("st.global.cs.v8.b32 [%0], {%1,%2,%3,%4,%5,%6,%7,%8};"
        :: "l"(p),
           "r"(__float_as_uint(r0.x)), "r"(__float_as_uint(r0.y)),
           "r"(__float_as_uint(r0.z)), "r"(__float_as_uint(r0.w)),
           "r"(__float_as_uint(r1.x)), "r"(__float_as_uint(r1.y)),
           "r"(__float_as_uint(r1.z)), "r"(__float_as_uint(r1.w))
        : "memory");
}

__global__ __launch_bounds__(TPB, 6)
void tri_mean_kernel(const float4* __restrict__ x, float4* __restrict__ out) {
    const int col2 = (blockIdx.x * TPB + threadIdx.x) * 2;  // float4 index, 0..L4-2
    const int bc   = blockIdx.y;                            // 0 .. 63

    const float4* __restrict__ xb = x   + (size_t)bc * NV * L4 + col2;
    float4* __restrict__ ob       = out + (size_t)bc * NT * L4 + col2;

    const float s = 1.0f / 3.0f;

    // Load both float4 halves of a vertex row chunk.
#define LD2(i, Va, Vb) do {                          \
        Va = xb[(size_t)(i) * L4];                   \
        Vb = xb[(size_t)(i) * L4 + 1];               \
    } while (0)

    // Emit one triangle row: mean of three vertex chunks, one STG.256.
#define EMIT2(t, Aa, Ab, Ba, Bb, Ca, Cb) do {        \
        float4 _r0, _r1;                             \
        _r0.x = ((Aa).x + (Ba).x + (Ca).x) * s;      \
        _r0.y = ((Aa).y + (Ba).y + (Ca).y) * s;      \
        _r0.z = ((Aa).z + (Ba).z + (Ca).z) * s;      \
        _r0.w = ((Aa).w + (Ba).w + (Ca).w) * s;      \
        _r1.x = ((Ab).x + (Bb).x + (Cb).x) * s;      \
        _r1.y = ((Ab).y + (Bb).y + (Cb).y) * s;      \
        _r1.z = ((Ab).z + (Bb).z + (Cb).z) * s;      \
        _r1.w = ((Ab).w + (Bb).w + (Cb).w) * s;      \
        stg256_cs(&ob[(size_t)(t) * L4], _r0, _r1);  \
    } while (0)

    // 2-row window, each vertex = pair of float4 (a = low half, b = high half).
    float4 A0a, A0b, A1a, A1b, A2a, A2b, A3a, A3b;
    float4 B0a, B0b, B1a, B1b, B2a, B2b, B3a, B3b;

    // Rows: r0(0,3) r1(3,4) r2(7,3) r3(10,4) r4(14,3) r5(17,4) r6(21,3)
    LD2(0, A0a, A0b); LD2(1, A1a, A1b); LD2(2, A2a, A2b);                    // r0
    LD2(3, B0a, B0b); LD2(4, B1a, B1b); LD2(5, B2a, B2b); LD2(6, B3a, B3b); // r1
    // band0: (0,3,4),(0,1,4),(1,4,5),(1,2,5),(2,5,6)
    EMIT2(0, A0a, A0b, B0a, B0b, B1a, B1b);
    EMIT2(1, A0a, A0b, A1a, A1b, B1a, B1b);
    EMIT2(2, A1a, A1b, B1a, B1b, B2a, B2b);
    EMIT2(3, A1a, A1b, A2a, A2b, B2a, B2b);
    EMIT2(4, A2a, A2b, B2a, B2b, B3a, B3b);

    // A<-r1(4); B<-r2(3)
    A0a = B0a; A0b = B0b; A1a = B1a; A1b = B1b;
    A2a = B2a; A2b = B2b; A3a = B3a; A3b = B3b;
    LD2(7, B0a, B0b); LD2(8, B1a, B1b); LD2(9, B2a, B2b);
    // band1: (3,4,7),(4,7,8),(4,5,8),(5,8,9),(5,6,9)
    EMIT2(5, A0a, A0b, A1a, A1b, B0a, B0b);
    EMIT2(6, A1a, A1b, B0a, B0b, B1a, B1b);
    EMIT2(7, A1a, A1b, A2a, A2b, B1a, B1b);
    EMIT2(8, A2a, A2b, B1a, B1b, B2a, B2b);
    EMIT2(9, A2a, A2b, A3a, A3b, B2a, B2b);

    // A<-r2(3); B<-r3(4)
    A0a = B0a; A0b = B0b; A1a = B1a; A1b = B1b; A2a = B2a; A2b = B2b;
    LD2(10, B0a, B0b); LD2(11, B1a, B1b); LD2(12, B2a, B2b); LD2(13, B3a, B3b);
    // band2: (7,10,11),(7,8,11),(8,11,12),(8,9,12),(9,12,13)
    EMIT2(10, A0a, A0b, B0a, B0b, B1a, B1b);
    EMIT2(11, A0a, A0b, A1a, A1b, B1a, B1b);
    EMIT2(12, A1a, A1b, B1a, B1b, B2a, B2b);
    EMIT2(13, A1a, A1b, A2a, A2b, B2a, B2b);
    EMIT2(14, A2a, A2b, B2a, B2b, B3a, B3b);

    // A<-r3(4); B<-r4(3)
    A0a = B0a; A0b = B0b; A1a = B1a; A1b = B1b;
    A2a = B2a; A2b = B2b; A3a = B3a; A3b = B3b;
    LD2(14, B0a, B0b); LD2(15, B1a, B1b); LD2(16, B2a, B2b);
    // band3: (10,11,14),(11,14,15),(11,12,15),(12,15,16),(12,13,16)
    EMIT2(15, A0a, A0b, A1a, A1b, B0a, B0b);
    EMIT2(16, A1a, A1b, B0a, B0b, B1a, B1b);
    EMIT2(17, A1a, A1b, A2a, A2b, B1a, B1b);
    EMIT2(18, A2a, A2b, B1a, B1b, B2a, B2b);
    EMIT2(19, A2a, A2b, A3a, A3b, B2a, B2b);

    // A<-r4(3); B<-r5(4)
    A0a = B0a; A0b = B0b; A1a = B1a; A1b = B1b; A2a = B2a; A2b = B2b;
    LD2(17, B0a, B0b); LD2(18, B1a, B1b); LD2(19, B2a, B2b); LD2(20, B3a, B3b);
    // band4: (14,17,18),(14,15,18),(15,18,19),(15,16,19),(16,19,20)
    EMIT2(20, A0a, A0b, B0a, B0b, B1a, B1b);
    EMIT2(21, A0a, A0b, A1a, A1b, B1a, B1b);
    EMIT2(22, A1a, A1b, B1a, B1b, B2a, B2b);
    EMIT2(23, A1a, A1b, A2a, A2b, B2a, B2b);
    EMIT2(24, A2a, A2b, B2a, B2b, B3a, B3b);

    // A<-r5(4); B<-r6(3)
    A0a = B0a; A0b = B0b; A1a = B1a; A1b = B1b;
    A2a = B2a; A2b = B2b; A3a = B3a; A3b = B3b;
    LD2(21, B0a, B0b); LD2(22, B1a, B1b); LD2(23, B2a, B2b);
    // band5: (17,18,21),(18,21,22),(18,19,22),(19,22,23),(19,20,23)
    EMIT2(25, A0a, A0b, A1a, A1b, B0a, B0b);
    EMIT2(26, A1a, A1b, B0a, B0b, B1a, B1b);
    EMIT2(27, A1a, A1b, A2a, A2b, B1a, B1b);
    EMIT2(28, A2a, A2b, B1a, B1b, B2a, B2b);
    EMIT2(29, A2a, A2b, A3a, A3b, B2a, B2b);

#undef LD2
#undef EMIT2
}

extern "C" void kernel_launch(void* const* d_in, const int* in_sizes, int n_in,
                              void* d_out, int out_size) {
    const float4* x = (const float4*)d_in[0];
    float4* out = (float4*)d_out;

    dim3 block(TPB);
    dim3 grid(L4 / (TPB * 2), 64);  // (32, 64) = 2048 blocks
    tri_mean_kernel<<<grid, block>>>(x, out);
}